// round 4
// baseline (speedup 1.0000x reference)
#include <cuda_runtime.h>
#include <cuda_bf16.h>
#include <cstdint>
#include <math.h>

#define BB 2
#define SS 2048
#define DD 1024
#define HH 16
#define HDim 64
#define NHZ (BB*HH)   // 32 (b,h) slices
#define LDA 18        // u32 per smem row (32 bf16 = 16 u32 + 2 pad)

// Scratch (allocation-free)
__device__ float g_q[(size_t)NHZ * SS * HDim];
__device__ float g_k[(size_t)NHZ * SS * HDim];
__device__ float g_v[(size_t)NHZ * SS * HDim];
__device__ float g_ao[(size_t)BB * SS * DD];

// ---------------------------------------------------------------------------
// mma.sync m16n8k16 bf16 (portable tensor path; tcgen05 unavailable on this
// toolchain target)
// ---------------------------------------------------------------------------
__device__ __forceinline__ void mma_bf16(float d[4], const uint32_t a[4], const uint32_t b[2]) {
    asm volatile(
        "mma.sync.aligned.m16n8k16.row.col.f32.bf16.bf16.f32 "
        "{%0,%1,%2,%3}, {%4,%5,%6,%7}, {%8,%9}, {%0,%1,%2,%3};"
        : "+f"(d[0]), "+f"(d[1]), "+f"(d[2]), "+f"(d[3])
        : "r"(a[0]), "r"(a[1]), "r"(a[2]), "r"(a[3]), "r"(b[0]), "r"(b[1]));
}

// fp32 -> (bf16 hi, bf16 lo) split, packing two values into u32 pairs
__device__ __forceinline__ void split_pack(float a, float b, uint32_t& hi, uint32_t& lo) {
    __nv_bfloat16 ah = __float2bfloat16(a);
    __nv_bfloat16 bh = __float2bfloat16(b);
    __nv_bfloat16 al = __float2bfloat16(a - __bfloat162float(ah));
    __nv_bfloat16 bl = __float2bfloat16(b - __bfloat162float(bh));
    hi = (uint32_t)__bfloat16_as_ushort(ah) | ((uint32_t)__bfloat16_as_ushort(bh) << 16);
    lo = (uint32_t)__bfloat16_as_ushort(al) | ((uint32_t)__bfloat16_as_ushort(bl) << 16);
}

// Load 128 rows x 32 fp32 (row-major, stride), split to bf16 hi/lo in smem
__device__ __forceinline__ void load_tile_rm(const float* __restrict__ src, int stride,
                                             uint32_t* __restrict__ hi,
                                             uint32_t* __restrict__ lo, int tid)
{
    const int c4 = tid & 7;     // 8 float4 = 32 floats per row
    const int r0 = tid >> 3;    // 32 rows per pass
    #pragma unroll
    for (int p = 0; p < 4; p++) {
        const int r = r0 + p * 32;
        float4 v = *(const float4*)(src + (size_t)r * stride + c4 * 4);
        uint32_t h0, l0, h1, l1;
        split_pack(v.x, v.y, h0, l0);
        split_pack(v.z, v.w, h1, l1);
        hi[r * LDA + c4 * 2]     = h0;
        hi[r * LDA + c4 * 2 + 1] = h1;
        lo[r * LDA + c4 * 2]     = l0;
        lo[r * LDA + c4 * 2 + 1] = l1;
    }
}

// Load V block [32 k][64 n] (row-major, stride HDim), transpose -> B[n][k] split
__device__ __forceinline__ void load_v_trans(const float* __restrict__ src,
                                             uint32_t* __restrict__ hi,
                                             uint32_t* __restrict__ lo, int tid)
{
    __nv_bfloat16* h16 = (__nv_bfloat16*)hi;
    __nv_bfloat16* l16 = (__nv_bfloat16*)lo;
    const int n = tid & 63;
    const int k0 = tid >> 6;    // 0..3
    #pragma unroll
    for (int p = 0; p < 8; p++) {
        const int k = k0 + p * 4;
        float v = src[(size_t)k * HDim + n];
        __nv_bfloat16 vh = __float2bfloat16(v);
        __nv_bfloat16 vl = __float2bfloat16(v - __bfloat162float(vh));
        h16[n * (LDA * 2) + k] = vh;
        l16[n * (LDA * 2) + k] = vl;
    }
}

// Fragment loads (m16n8k16 thread mapping; kp = k-pair base = ks*8 u32)
__device__ __forceinline__ void lda_frag(const uint32_t* S, int r, int kp, int l, uint32_t a[4]) {
    const uint32_t* p = S + (size_t)(r + (l >> 2)) * LDA + kp + (l & 3);
    a[0] = p[0];
    a[1] = p[8 * LDA];
    a[2] = p[4];
    a[3] = p[8 * LDA + 4];
}
__device__ __forceinline__ void ldb_frag(const uint32_t* S, int n, int kp, int l, uint32_t b[2]) {
    const uint32_t* p = S + (size_t)(n + (l >> 2)) * LDA + kp + (l & 3);
    b[0] = p[0];
    b[1] = p[4];
}

// ---------------------------------------------------------------------------
// Projection: Y = X @ W^T + bias ; M=4096, N=1024, K=1024. Tile 128x128, BK=32.
// 8 warps, warp tile 32x64 (wm = w&3, wn = w>>2).
// ---------------------------------------------------------------------------
template <bool SPLIT>
__global__ __launch_bounds__(256) void proj_mma(
    const float* __restrict__ X, const float* __restrict__ W,
    const float* __restrict__ bias, float* __restrict__ Y)
{
    __shared__ uint32_t Ahi[128 * LDA], Alo[128 * LDA], Bhi[128 * LDA], Blo[128 * LDA];
    const int tid = threadIdx.x, w = tid >> 5, l = tid & 31;
    const int m0 = blockIdx.y << 7, n0 = blockIdx.x << 7;
    const int wm = (w & 3) * 32, wn = (w >> 2) * 64;

    float acc[2][8][4] = {};

    for (int c = 0; c < DD / 32; c++) {
        load_tile_rm(X + (size_t)m0 * DD + c * 32, DD, Ahi, Alo, tid);
        load_tile_rm(W + (size_t)n0 * DD + c * 32, DD, Bhi, Blo, tid);
        __syncthreads();
        #pragma unroll
        for (int ks = 0; ks < 2; ks++) {
            const int kp = ks * 8;
            uint32_t ah[2][4], al[2][4];
            #pragma unroll
            for (int mi = 0; mi < 2; mi++) {
                lda_frag(Ahi, wm + mi * 16, kp, l, ah[mi]);
                lda_frag(Alo, wm + mi * 16, kp, l, al[mi]);
            }
            #pragma unroll
            for (int ni = 0; ni < 8; ni++) {
                uint32_t bh[2], bl[2];
                ldb_frag(Bhi, wn + ni * 8, kp, l, bh);
                ldb_frag(Blo, wn + ni * 8, kp, l, bl);
                #pragma unroll
                for (int mi = 0; mi < 2; mi++) {
                    mma_bf16(acc[mi][ni], ah[mi], bh);
                    mma_bf16(acc[mi][ni], ah[mi], bl);
                    mma_bf16(acc[mi][ni], al[mi], bh);
                }
            }
        }
        __syncthreads();
    }

    #pragma unroll
    for (int mi = 0; mi < 2; mi++) {
        #pragma unroll
        for (int ni = 0; ni < 8; ni++) {
            const int r  = m0 + wm + mi * 16 + (l >> 2);
            const int cc = n0 + wn + ni * 8 + (l & 3) * 2;
            const float b0 = __ldg(bias + cc), b1 = __ldg(bias + cc + 1);
            float2 o0 = make_float2(acc[mi][ni][0] + b0, acc[mi][ni][1] + b1);
            float2 o1 = make_float2(acc[mi][ni][2] + b0, acc[mi][ni][3] + b1);
            if (SPLIT) {
                const int h = cc >> 6, hd = cc & 63;
                const int b_ = r >> 11, s0 = r & (SS - 1), s1 = (r + 8) & (SS - 1);
                *(float2*)(Y + (((size_t)b_ * HH + h) * SS + s0) * HDim + hd) = o0;
                *(float2*)(Y + (((size_t)b_ * HH + h) * SS + s1) * HDim + hd) = o1;
            } else {
                *(float2*)(Y + (size_t)r * DD + cc) = o0;
                *(float2*)(Y + (size_t)(r + 8) * DD + cc) = o1;
            }
        }
    }
}

// ---------------------------------------------------------------------------
// Scores: P[z] = (Q[z] @ K[z]^T) * 0.125 ; per z: M=N=2048, K=64.
// ---------------------------------------------------------------------------
__global__ __launch_bounds__(256) void scores_mma(
    const float* __restrict__ Q, const float* __restrict__ Km, float* __restrict__ P)
{
    __shared__ uint32_t Ahi[128 * LDA], Alo[128 * LDA], Bhi[128 * LDA], Blo[128 * LDA];
    const int tid = threadIdx.x, w = tid >> 5, l = tid & 31;
    const int z = blockIdx.z;
    const int m0 = blockIdx.y << 7, n0 = blockIdx.x << 7;
    const int wm = (w & 3) * 32, wn = (w >> 2) * 64;
    const float* Qz = Q + (size_t)z * SS * HDim;
    const float* Kz = Km + (size_t)z * SS * HDim;

    float acc[2][8][4] = {};

    #pragma unroll
    for (int c = 0; c < 2; c++) {
        load_tile_rm(Qz + (size_t)m0 * HDim + c * 32, HDim, Ahi, Alo, tid);
        load_tile_rm(Kz + (size_t)n0 * HDim + c * 32, HDim, Bhi, Blo, tid);
        __syncthreads();
        #pragma unroll
        for (int ks = 0; ks < 2; ks++) {
            const int kp = ks * 8;
            uint32_t ah[2][4], al[2][4];
            #pragma unroll
            for (int mi = 0; mi < 2; mi++) {
                lda_frag(Ahi, wm + mi * 16, kp, l, ah[mi]);
                lda_frag(Alo, wm + mi * 16, kp, l, al[mi]);
            }
            #pragma unroll
            for (int ni = 0; ni < 8; ni++) {
                uint32_t bh[2], bl[2];
                ldb_frag(Bhi, wn + ni * 8, kp, l, bh);
                ldb_frag(Blo, wn + ni * 8, kp, l, bl);
                #pragma unroll
                for (int mi = 0; mi < 2; mi++) {
                    mma_bf16(acc[mi][ni], ah[mi], bh);
                    mma_bf16(acc[mi][ni], ah[mi], bl);
                    mma_bf16(acc[mi][ni], al[mi], bh);
                }
            }
        }
        __syncthreads();
    }

    float* Pz = P + (size_t)z * SS * SS;
    #pragma unroll
    for (int mi = 0; mi < 2; mi++) {
        #pragma unroll
        for (int ni = 0; ni < 8; ni++) {
            const int r  = m0 + wm + mi * 16 + (l >> 2);
            const int cc = n0 + wn + ni * 8 + (l & 3) * 2;
            float2 o0 = make_float2(acc[mi][ni][0] * 0.125f, acc[mi][ni][1] * 0.125f);
            float2 o1 = make_float2(acc[mi][ni][2] * 0.125f, acc[mi][ni][3] * 0.125f);
            *(float2*)(Pz + (size_t)r * SS + cc) = o0;
            *(float2*)(Pz + (size_t)(r + 8) * SS + cc) = o1;
        }
    }
}

// ---------------------------------------------------------------------------
// AV: AO = P @ V per z ; M=2048, N=64, K=2048. Tile 128x64, BK=32 (64 chunks).
// 8 warps, warp tile 16x64.
// ---------------------------------------------------------------------------
__global__ __launch_bounds__(256) void av_mma(
    const float* __restrict__ P, const float* __restrict__ V, float* __restrict__ AO)
{
    __shared__ uint32_t Ahi[128 * LDA], Alo[128 * LDA], Bhi[64 * LDA], Blo[64 * LDA];
    const int tid = threadIdx.x, w = tid >> 5, l = tid & 31;
    const int z = blockIdx.y;
    const int b = z / HH, h = z % HH;
    const int m0 = blockIdx.x << 7;
    const int wm = w * 16;
    const float* Pz = P + (size_t)z * SS * SS;
    const float* Vz = V + (size_t)z * SS * HDim;

    float acc[8][4] = {};

    for (int c = 0; c < SS / 32; c++) {
        load_tile_rm(Pz + (size_t)m0 * SS + c * 32, SS, Ahi, Alo, tid);
        load_v_trans(Vz + (size_t)c * 32 * HDim, Bhi, Blo, tid);
        __syncthreads();
        #pragma unroll
        for (int ks = 0; ks < 2; ks++) {
            const int kp = ks * 8;
            uint32_t ah[4], al[4];
            lda_frag(Ahi, wm, kp, l, ah);
            lda_frag(Alo, wm, kp, l, al);
            #pragma unroll
            for (int ni = 0; ni < 8; ni++) {
                uint32_t bh[2], bl[2];
                ldb_frag(Bhi, ni * 8, kp, l, bh);
                ldb_frag(Blo, ni * 8, kp, l, bl);
                mma_bf16(acc[ni], ah, bh);
                mma_bf16(acc[ni], ah, bl);
                mma_bf16(acc[ni], al, bh);
            }
        }
        __syncthreads();
    }

    #pragma unroll
    for (int ni = 0; ni < 8; ni++) {
        const int r  = m0 + wm + (l >> 2);
        const int cc = ni * 8 + (l & 3) * 2;
        *(float2*)(AO + ((size_t)b * SS + r) * DD + h * HDim + cc) =
            make_float2(acc[ni][0], acc[ni][1]);
        *(float2*)(AO + ((size_t)b * SS + r + 8) * DD + h * HDim + cc) =
            make_float2(acc[ni][2], acc[ni][3]);
    }
}

// ---------------------------------------------------------------------------
// Row softmax in-place, float4 + shfl reductions. One block per 2048-row.
// ---------------------------------------------------------------------------
__global__ __launch_bounds__(256) void softmax_kernel(float* __restrict__ P)
{
    const size_t row = blockIdx.x;
    float4* p = (float4*)(P + row * (size_t)SS);
    const int t = threadIdx.x;
    float4 a = p[t];
    float4 b = p[t + 256];
    float mx = fmaxf(fmaxf(fmaxf(a.x, a.y), fmaxf(a.z, a.w)),
                     fmaxf(fmaxf(b.x, b.y), fmaxf(b.z, b.w)));
    #pragma unroll
    for (int o = 16; o > 0; o >>= 1) mx = fmaxf(mx, __shfl_xor_sync(0xFFFFFFFFu, mx, o));
    __shared__ float rmax[8], rsum[8];
    if ((t & 31) == 0) rmax[t >> 5] = mx;
    __syncthreads();
    mx = fmaxf(fmaxf(fmaxf(rmax[0], rmax[1]), fmaxf(rmax[2], rmax[3])),
               fmaxf(fmaxf(rmax[4], rmax[5]), fmaxf(rmax[6], rmax[7])));
    a.x = __expf(a.x - mx); a.y = __expf(a.y - mx);
    a.z = __expf(a.z - mx); a.w = __expf(a.w - mx);
    b.x = __expf(b.x - mx); b.y = __expf(b.y - mx);
    b.z = __expf(b.z - mx); b.w = __expf(b.w - mx);
    float s = a.x + a.y + a.z + a.w + b.x + b.y + b.z + b.w;
    #pragma unroll
    for (int o = 16; o > 0; o >>= 1) s += __shfl_xor_sync(0xFFFFFFFFu, s, o);
    if ((t & 31) == 0) rsum[t >> 5] = s;
    __syncthreads();
    s = rsum[0] + rsum[1] + rsum[2] + rsum[3] + rsum[4] + rsum[5] + rsum[6] + rsum[7];
    const float inv = 1.0f / s;
    a.x *= inv; a.y *= inv; a.z *= inv; a.w *= inv;
    b.x *= inv; b.y *= inv; b.z *= inv; b.w *= inv;
    p[t] = a;
    p[t + 256] = b;
}

// ---------------------------------------------------------------------------
// Launch
// ---------------------------------------------------------------------------
extern "C" void kernel_launch(void* const* d_in, const int* in_sizes, int n_in,
                              void* d_out, int out_size)
{
    const float* query = (const float*)d_in[0];
    const float* key_  = (const float*)d_in[1];
    const float* value = (const float*)d_in[2];
    const float* wq = (const float*)d_in[3];
    const float* bq = (const float*)d_in[4];
    const float* wk = (const float*)d_in[5];
    const float* bk = (const float*)d_in[6];
    const float* wv = (const float*)d_in[7];
    const float* bv = (const float*)d_in[8];
    const float* wo = (const float*)d_in[9];
    const float* bo = (const float*)d_in[10];

    float* out = (float*)d_out;                          // (B,S,D)
    float* attnw = out + (size_t)BB * SS * DD;           // (B,H,S,S)

    float *gq, *gk, *gv, *gao;
    cudaGetSymbolAddress((void**)&gq, g_q);
    cudaGetSymbolAddress((void**)&gk, g_k);
    cudaGetSymbolAddress((void**)&gv, g_v);
    cudaGetSymbolAddress((void**)&gao, g_ao);

    const dim3 gproj(DD / 128, (BB * SS) / 128);         // (8, 32)
    proj_mma<true><<<gproj, 256>>>(query, wq, bq, gq);
    proj_mma<true><<<gproj, 256>>>(key_, wk, bk, gk);
    proj_mma<true><<<gproj, 256>>>(value, wv, bv, gv);

    scores_mma<<<dim3(SS / 128, SS / 128, NHZ), 256>>>(gq, gk, attnw);

    softmax_kernel<<<NHZ * SS, 256>>>(attnw);

    av_mma<<<dim3(SS / 128, NHZ), 256>>>(attnw, gv, gao);

    proj_mma<false><<<gproj, 256>>>(gao, wo, bo, out);
}

// round 5
// speedup vs baseline: 1.4967x; 1.4967x over previous
#include <cuda_runtime.h>
#include <cuda_bf16.h>
#include <cstdint>
#include <math.h>

#define BB 2
#define SS 2048
#define DD 1024
#define HH 16
#define HDim 64
#define NHZ (BB*HH)

// Packed scratch: u32 = bf16_hi | bf16_lo<<16
__device__ uint32_t g_xq[4194304], g_xk[4194304], g_xv[4194304];
__device__ uint32_t g_wq[1048576], g_wk[1048576], g_wv[1048576], g_wo[1048576];
__device__ uint32_t g_qp[4194304];   // Q packed (z,s,hd)
__device__ uint32_t g_kp[4194304];   // K packed (z,s,hd)
__device__ uint32_t g_vt[4194304];   // V packed transposed (z,hd,s)
__device__ uint32_t g_aop[4194304];  // attn_output packed (b,s,d)

__device__ __forceinline__ void mma_bf16(float d[4], const uint32_t a[4], const uint32_t b[2]) {
    asm volatile(
        "mma.sync.aligned.m16n8k16.row.col.f32.bf16.bf16.f32 "
        "{%0,%1,%2,%3}, {%4,%5,%6,%7}, {%8,%9}, {%0,%1,%2,%3};"
        : "+f"(d[0]), "+f"(d[1]), "+f"(d[2]), "+f"(d[3])
        : "r"(a[0]), "r"(a[1]), "r"(a[2]), "r"(a[3]), "r"(b[0]), "r"(b[1]));
}
__device__ __forceinline__ uint32_t packf(float x) {
    __nv_bfloat16 h = __float2bfloat16(x);
    __nv_bfloat16 l = __float2bfloat16(x - __bfloat162float(h));
    return (uint32_t)__bfloat16_as_ushort(h) | ((uint32_t)__bfloat16_as_ushort(l) << 16);
}
__device__ __forceinline__ void cpa16(uint32_t dst, const void* src) {
    asm volatile("cp.async.cg.shared.global [%0], [%1], 16;" :: "r"(dst), "l"(src));
}
#define CP_COMMIT() asm volatile("cp.async.commit_group;" ::: "memory")
#define CP_WAIT1() asm volatile("cp.async.wait_group 1;" ::: "memory")
#define CP_WAIT0() asm volatile("cp.async.wait_group 0;" ::: "memory")

// Fragment loads from packed smem; 1 PRMT per output register.
__device__ __forceinline__ void lda_pk(const uint32_t* S, int lda, int r, int ks, int l,
                                       uint32_t ah[4], uint32_t al[4]) {
    const uint32_t* p = S + (r + (l >> 2)) * lda + ks * 16 + 2 * (l & 3);
    uint2 q0 = *(const uint2*)p;
    uint2 q1 = *(const uint2*)(p + 8);
    uint2 q2 = *(const uint2*)(p + 8 * lda);
    uint2 q3 = *(const uint2*)(p + 8 * lda + 8);
    ah[0] = __byte_perm(q0.x, q0.y, 0x5410); al[0] = __byte_perm(q0.x, q0.y, 0x7632);
    ah[1] = __byte_perm(q2.x, q2.y, 0x5410); al[1] = __byte_perm(q2.x, q2.y, 0x7632);
    ah[2] = __byte_perm(q1.x, q1.y, 0x5410); al[2] = __byte_perm(q1.x, q1.y, 0x7632);
    ah[3] = __byte_perm(q3.x, q3.y, 0x5410); al[3] = __byte_perm(q3.x, q3.y, 0x7632);
}
__device__ __forceinline__ void ldb_pk(const uint32_t* S, int lda, int n, int ks, int l,
                                       uint32_t bh[2], uint32_t bl[2]) {
    const uint32_t* p = S + (n + (l >> 2)) * lda + ks * 16 + 2 * (l & 3);
    uint2 q0 = *(const uint2*)p;
    uint2 q1 = *(const uint2*)(p + 8);
    bh[0] = __byte_perm(q0.x, q0.y, 0x5410); bl[0] = __byte_perm(q0.x, q0.y, 0x7632);
    bh[1] = __byte_perm(q1.x, q1.y, 0x5410); bl[1] = __byte_perm(q1.x, q1.y, 0x7632);
}

__global__ void pack_kernel(const float4* __restrict__ src, uint4* __restrict__ dst, int n4) {
    int i = blockIdx.x * 256 + threadIdx.x;
    if (i < n4) {
        float4 v = src[i];
        dst[i] = make_uint4(packf(v.x), packf(v.y), packf(v.z), packf(v.w));
    }
}

// ---------------------------------------------------------------------------
// Projection: Y = X@W^T + bias. M=4096,N=1024,K=1024. Tile 128x64, BK=32,
// 8 warps (4m x 2n), warp 32x32. Double-buffered cp.async A+B.
// MODE 0: packed (z,s,hd); MODE 1: packed transposed (z,hd,s); MODE 2: fp32 rm.
// ---------------------------------------------------------------------------
#define PJ_AW (128*40)
#define PJ_BW (64*40)
#define PJ_SM ((2*PJ_AW + 2*PJ_BW)*4)

template <int MODE>
__global__ __launch_bounds__(256, 2) void proj_mma(
    const uint32_t* __restrict__ Xp, const uint32_t* __restrict__ Wp,
    const float* __restrict__ bias, void* __restrict__ Yv)
{
    extern __shared__ uint32_t sm[];
    const uint32_t sb = (uint32_t)__cvta_generic_to_shared(sm);
    const int tid = threadIdx.x, w = tid >> 5, l = tid & 31;
    const int m0 = blockIdx.y << 7, n0 = blockIdx.x << 6;
    const int wm = (w & 3) << 5, wn = (w >> 2) << 5;

    auto stage = [&](int c) {
        const int bi = c & 1;
        const uint32_t aB = sb + bi * (PJ_AW * 4);
        #pragma unroll
        for (int i = 0; i < 4; i++) {
            int g = tid + (i << 8), row = g >> 3, q = g & 7;
            cpa16(aB + (uint32_t)(row * 40 + q * 4) * 4,
                  Xp + (size_t)(m0 + row) * DD + c * 32 + q * 4);
        }
        const uint32_t bB = sb + (2 * PJ_AW + bi * PJ_BW) * 4;
        #pragma unroll
        for (int i = 0; i < 2; i++) {
            int g = tid + (i << 8), row = g >> 3, q = g & 7;
            cpa16(bB + (uint32_t)(row * 40 + q * 4) * 4,
                  Wp + (size_t)(n0 + row) * DD + c * 32 + q * 4);
        }
        CP_COMMIT();
    };
    stage(0); stage(1);

    float acc[2][4][4] = {};
    for (int c = 0; c < 32; c++) {
        if (c < 31) CP_WAIT1(); else CP_WAIT0();
        __syncthreads();
        const uint32_t* As = sm + (c & 1) * PJ_AW;
        const uint32_t* Bs = sm + 2 * PJ_AW + (c & 1) * PJ_BW;
        #pragma unroll
        for (int ks = 0; ks < 2; ks++) {
            uint32_t ah[2][4], al[2][4];
            lda_pk(As, 40, wm, ks, l, ah[0], al[0]);
            lda_pk(As, 40, wm + 16, ks, l, ah[1], al[1]);
            #pragma unroll
            for (int ni = 0; ni < 4; ni++) {
                uint32_t bh[2], bl[2];
                ldb_pk(Bs, 40, wn + ni * 8, ks, l, bh, bl);
                #pragma unroll
                for (int mi = 0; mi < 2; mi++) {
                    mma_bf16(acc[mi][ni], ah[mi], bh);
                    mma_bf16(acc[mi][ni], ah[mi], bl);
                    mma_bf16(acc[mi][ni], al[mi], bh);
                }
            }
        }
        __syncthreads();
        if (c + 2 < 32) stage(c + 2);
    }

    #pragma unroll
    for (int mi = 0; mi < 2; mi++) {
        #pragma unroll
        for (int ni = 0; ni < 4; ni++) {
            const int r = m0 + wm + mi * 16 + (l >> 2);
            const int cc = n0 + wn + ni * 8 + 2 * (l & 3);
            const float b0 = __ldg(bias + cc), b1 = __ldg(bias + cc + 1);
            float y00 = acc[mi][ni][0] + b0, y01 = acc[mi][ni][1] + b1;
            float y10 = acc[mi][ni][2] + b0, y11 = acc[mi][ni][3] + b1;
            if (MODE == 2) {
                float* O = (float*)Yv;
                *(float2*)(O + (size_t)r * DD + cc) = make_float2(y00, y01);
                *(float2*)(O + (size_t)(r + 8) * DD + cc) = make_float2(y10, y11);
            } else {
                uint32_t* Y = (uint32_t*)Yv;
                const int b_ = r >> 11, s = r & (SS - 1), h = cc >> 6, hd = cc & 63;
                if (MODE == 0) {
                    size_t zb = (size_t)(b_ * HH + h) * SS;
                    *(uint2*)(Y + (zb + s) * HDim + hd) = make_uint2(packf(y00), packf(y01));
                    *(uint2*)(Y + (zb + s + 8) * HDim + hd) = make_uint2(packf(y10), packf(y11));
                } else {
                    size_t zb = (size_t)(b_ * HH + h) * HDim;
                    Y[(zb + hd) * SS + s]         = packf(y00);
                    Y[(zb + hd + 1) * SS + s]     = packf(y01);
                    Y[(zb + hd) * SS + s + 8]     = packf(y10);
                    Y[(zb + hd + 1) * SS + s + 8] = packf(y11);
                }
            }
        }
    }
}

// ---------------------------------------------------------------------------
// Scores: P = (Q K^T)*0.125. CTA = 64-row strip, loops 16 n-tiles of 128.
// A (64x64 words) resident; B double-buffered. 8 warps (2m x 4n), warp 32x32.
// ---------------------------------------------------------------------------
#define SC_AW (64*72)
#define SC_BW (128*72)
#define SC_SM ((SC_AW + 2*SC_BW)*4)

__global__ __launch_bounds__(256) void scores_mma(
    const uint32_t* __restrict__ Qp, const uint32_t* __restrict__ Kp,
    float* __restrict__ P)
{
    extern __shared__ uint32_t sm[];
    const uint32_t sb = (uint32_t)__cvta_generic_to_shared(sm);
    const int tid = threadIdx.x, w = tid >> 5, l = tid & 31;
    const int z = blockIdx.y, m0 = blockIdx.x << 6;
    const int wm = (w & 1) << 5, wn = (w >> 1) << 5;

    auto stageB = [&](int nt) {
        const uint32_t bB = sb + (SC_AW + (nt & 1) * SC_BW) * 4;
        #pragma unroll
        for (int i = 0; i < 8; i++) {
            int g = tid + (i << 8), row = g >> 4, q = g & 15;
            cpa16(bB + (uint32_t)(row * 72 + q * 4) * 4,
                  Kp + ((size_t)z * SS + nt * 128 + row) * HDim + q * 4);
        }
    };
    #pragma unroll
    for (int i = 0; i < 4; i++) {   // A: 64 rows x 64 words
        int g = tid + (i << 8), row = g >> 4, q = g & 15;
        cpa16(sb + (uint32_t)(row * 72 + q * 4) * 4,
              Qp + ((size_t)z * SS + m0 + row) * HDim + q * 4);
    }
    stageB(0); CP_COMMIT();
    stageB(1); CP_COMMIT();

    float* Pz = P + (size_t)z * SS * SS;
    for (int nt = 0; nt < 16; nt++) {
        if (nt < 15) CP_WAIT1(); else CP_WAIT0();
        __syncthreads();
        const uint32_t* Bs = sm + SC_AW + (nt & 1) * SC_BW;
        float acc[2][4][4] = {};
        #pragma unroll
        for (int ks = 0; ks < 4; ks++) {
            uint32_t ah[2][4], al[2][4];
            lda_pk(sm, 72, wm, ks, l, ah[0], al[0]);
            lda_pk(sm, 72, wm + 16, ks, l, ah[1], al[1]);
            #pragma unroll
            for (int ni = 0; ni < 4; ni++) {
                uint32_t bh[2], bl[2];
                ldb_pk(Bs, 72, wn + ni * 8, ks, l, bh, bl);
                #pragma unroll
                for (int mi = 0; mi < 2; mi++) {
                    mma_bf16(acc[mi][ni], ah[mi], bh);
                    mma_bf16(acc[mi][ni], ah[mi], bl);
                    mma_bf16(acc[mi][ni], al[mi], bh);
                }
            }
        }
        __syncthreads();
        if (nt + 2 < 16) { stageB(nt + 2); CP_COMMIT(); }
        #pragma unroll
        for (int mi = 0; mi < 2; mi++) {
            #pragma unroll
            for (int ni = 0; ni < 4; ni++) {
                const int r = m0 + wm + mi * 16 + (l >> 2);
                const int cc = nt * 128 + wn + ni * 8 + 2 * (l & 3);
                *(float2*)(Pz + (size_t)r * SS + cc) =
                    make_float2(acc[mi][ni][0] * 0.125f, acc[mi][ni][1] * 0.125f);
                *(float2*)(Pz + (size_t)(r + 8) * SS + cc) =
                    make_float2(acc[mi][ni][2] * 0.125f, acc[mi][ni][3] * 0.125f);
            }
        }
    }
}

// ---------------------------------------------------------------------------
// AV: AO = P @ V. Tile 128x64, BK=64 (32 chunks). A converted fp32->packed
// in-kernel (register-prefetched); B (V transposed, packed) cp.async.
// 8 warps, warp 16x64. Writes packed AO.
// ---------------------------------------------------------------------------
#define AV_AW (128*72)
#define AV_BW (64*72)
#define AV_SM ((AV_AW + 2*AV_BW)*4)

__global__ __launch_bounds__(256, 2) void av_mma(
    const float* __restrict__ P, const uint32_t* __restrict__ Vt,
    uint32_t* __restrict__ AOp)
{
    extern __shared__ uint32_t sm[];
    const uint32_t sb = (uint32_t)__cvta_generic_to_shared(sm);
    const int tid = threadIdx.x, w = tid >> 5, l = tid & 31;
    const int z = blockIdx.y, b = z >> 4, h = z & 15;
    const int m0 = blockIdx.x << 7;
    const int wm = w << 4;
    const float* Pz = P + (size_t)z * SS * SS;
    const uint32_t* Vz = Vt + (size_t)z * HDim * SS;

    auto stageB = [&](int c) {
        const uint32_t bB = sb + (AV_AW + (c & 1) * AV_BW) * 4;
        #pragma unroll
        for (int i = 0; i < 4; i++) {
            int g = tid + (i << 8), row = g >> 4, q = g & 15;
            cpa16(bB + (uint32_t)(row * 72 + q * 4) * 4,
                  Vz + (size_t)row * SS + c * 64 + q * 4);
        }
        CP_COMMIT();
    };
    stageB(0); stageB(1);

    const int arow = tid >> 1, aq = (tid & 1) << 3;   // each thread: 1 row, 8 floats x4? no:
    // A tile: 128 rows x 64 floats = 2048 float4; 256 threads -> 8 float4 each.
    float acc[8][4] = {};
    for (int c = 0; c < 32; c++) {
        // prefetch A fp32 into regs
        float4 av[8];
        #pragma unroll
        for (int i = 0; i < 8; i++) {
            int g = tid + (i << 8), row = g >> 4, q = g & 15;
            av[i] = *(const float4*)(Pz + (size_t)(m0 + row) * SS + c * 64 + q * 4);
        }
        if (c < 31) CP_WAIT1(); else CP_WAIT0();
        __syncthreads();
        #pragma unroll
        for (int i = 0; i < 8; i++) {
            int g = tid + (i << 8), row = g >> 4, q = g & 15;
            sm[row * 72 + q * 4 + 0] = packf(av[i].x);
            sm[row * 72 + q * 4 + 1] = packf(av[i].y);
            sm[row * 72 + q * 4 + 2] = packf(av[i].z);
            sm[row * 72 + q * 4 + 3] = packf(av[i].w);
        }
        __syncthreads();
        const uint32_t* Bs = sm + AV_AW + (c & 1) * AV_BW;
        #pragma unroll
        for (int ks = 0; ks < 4; ks++) {
            uint32_t ah[4], al[4];
            lda_pk(sm, 72, wm, ks, l, ah, al);
            #pragma unroll
            for (int ni = 0; ni < 8; ni++) {
                uint32_t bh[2], bl[2];
                ldb_pk(Bs, 72, ni * 8, ks, l, bh, bl);
                mma_bf16(acc[ni], ah, bh);
                mma_bf16(acc[ni], ah, bl);
                mma_bf16(acc[ni], al, bh);
            }
        }
        __syncthreads();
        if (c + 2 < 32) stageB(c + 2);
    }

    #pragma unroll
    for (int ni = 0; ni < 8; ni++) {
        const int r = m0 + wm + (l >> 2);
        const int cc = ni * 8 + 2 * (l & 3);
        uint32_t* dst = AOp + ((size_t)b * SS + r) * DD + h * HDim + cc;
        *(uint2*)dst = make_uint2(packf(acc[ni][0]), packf(acc[ni][1]));
        *(uint2*)(dst + 8 * DD) = make_uint2(packf(acc[ni][2]), packf(acc[ni][3]));
    }
}

// ---------------------------------------------------------------------------
// Row softmax in-place (fp32 P), one block per 2048-row.
// ---------------------------------------------------------------------------
__global__ __launch_bounds__(256) void softmax_kernel(float* __restrict__ P)
{
    const size_t row = blockIdx.x;
    float4* p = (float4*)(P + row * (size_t)SS);
    const int t = threadIdx.x;
    float4 a = p[t];
    float4 b = p[t + 256];
    float mx = fmaxf(fmaxf(fmaxf(a.x, a.y), fmaxf(a.z, a.w)),
                     fmaxf(fmaxf(b.x, b.y), fmaxf(b.z, b.w)));
    #pragma unroll
    for (int o = 16; o > 0; o >>= 1) mx = fmaxf(mx, __shfl_xor_sync(0xFFFFFFFFu, mx, o));
    __shared__ float rmax[8], rsum[8];
    if ((t & 31) == 0) rmax[t >> 5] = mx;
    __syncthreads();
    mx = fmaxf(fmaxf(fmaxf(rmax[0], rmax[1]), fmaxf(rmax[2], rmax[3])),
               fmaxf(fmaxf(rmax[4], rmax[5]), fmaxf(rmax[6], rmax[7])));
    a.x = __expf(a.x - mx); a.y = __expf(a.y - mx);
    a.z = __expf(a.z - mx); a.w = __expf(a.w - mx);
    b.x = __expf(b.x - mx); b.y = __expf(b.y - mx);
    b.z = __expf(b.z - mx); b.w = __expf(b.w - mx);
    float s = a.x + a.y + a.z + a.w + b.x + b.y + b.z + b.w;
    #pragma unroll
    for (int o = 16; o > 0; o >>= 1) s += __shfl_xor_sync(0xFFFFFFFFu, s, o);
    if ((t & 31) == 0) rsum[t >> 5] = s;
    __syncthreads();
    s = rsum[0] + rsum[1] + rsum[2] + rsum[3] + rsum[4] + rsum[5] + rsum[6] + rsum[7];
    const float inv = 1.0f / s;
    a.x *= inv; a.y *= inv; a.z *= inv; a.w *= inv;
    b.x *= inv; b.y *= inv; b.z *= inv; b.w *= inv;
    p[t] = a;
    p[t + 256] = b;
}

// ---------------------------------------------------------------------------
extern "C" void kernel_launch(void* const* d_in, const int* in_sizes, int n_in,
                              void* d_out, int out_size)
{
    const float* query = (const float*)d_in[0];
    const float* key_  = (const float*)d_in[1];
    const float* value = (const float*)d_in[2];
    const float* wq = (const float*)d_in[3];
    const float* bq = (const float*)d_in[4];
    const float* wk = (const float*)d_in[5];
    const float* bk = (const float*)d_in[6];
    const float* wv = (const float*)d_in[7];
    const float* bv = (const float*)d_in[8];
    const float* wo = (const float*)d_in[9];
    const float* bo = (const float*)d_in[10];

    float* out = (float*)d_out;                 // (B,S,D)
    float* attnw = out + (size_t)BB * SS * DD;  // (B,H,S,S)

    uint32_t *xq, *xk, *xv, *pwq, *pwk, *pwv, *pwo, *qp, *kp, *vt, *aop;
    cudaGetSymbolAddress((void**)&xq, g_xq);
    cudaGetSymbolAddress((void**)&xk, g_xk);
    cudaGetSymbolAddress((void**)&xv, g_xv);
    cudaGetSymbolAddress((void**)&pwq, g_wq);
    cudaGetSymbolAddress((void**)&pwk, g_wk);
    cudaGetSymbolAddress((void**)&pwv, g_wv);
    cudaGetSymbolAddress((void**)&pwo, g_wo);
    cudaGetSymbolAddress((void**)&qp, g_qp);
    cudaGetSymbolAddress((void**)&kp, g_kp);
    cudaGetSymbolAddress((void**)&vt, g_vt);
    cudaGetSymbolAddress((void**)&aop, g_aop);

    static int done = 0;
    if (!done) {
        cudaFuncSetAttribute(proj_mma<0>, cudaFuncAttributeMaxDynamicSharedMemorySize, PJ_SM);
        cudaFuncSetAttribute(proj_mma<1>, cudaFuncAttributeMaxDynamicSharedMemorySize, PJ_SM);
        cudaFuncSetAttribute(proj_mma<2>, cudaFuncAttributeMaxDynamicSharedMemorySize, PJ_SM);
        cudaFuncSetAttribute(scores_mma,  cudaFuncAttributeMaxDynamicSharedMemorySize, SC_SM);
        cudaFuncSetAttribute(av_mma,      cudaFuncAttributeMaxDynamicSharedMemorySize, AV_SM);
        done = 1;
    }

    const int nin4 = (BB * SS * DD) / 4;   // 1048576
    const int nw4  = (DD * DD) / 4;        // 262144
    pack_kernel<<<nin4 / 256, 256>>>((const float4*)query, (uint4*)xq, nin4);
    pack_kernel<<<nin4 / 256, 256>>>((const float4*)key_,  (uint4*)xk, nin4);
    pack_kernel<<<nin4 / 256, 256>>>((const float4*)value, (uint4*)xv, nin4);
    pack_kernel<<<nw4 / 256, 256>>>((const float4*)wq, (uint4*)pwq, nw4);
    pack_kernel<<<nw4 / 256, 256>>>((const float4*)wk, (uint4*)pwk, nw4);
    pack_kernel<<<nw4 / 256, 256>>>((const float4*)wv, (uint4*)pwv, nw4);
    pack_kernel<<<nw4 / 256, 256>>>((const float4*)wo, (uint4*)pwo, nw4);

    const dim3 gproj(DD / 64, (BB * SS) / 128);   // (16, 32)
    proj_mma<0><<<gproj, 256, PJ_SM>>>(xq, pwq, bq, qp);
    proj_mma<0><<<gproj, 256, PJ_SM>>>(xk, pwk, bk, kp);
    proj_mma<1><<<gproj, 256, PJ_SM>>>(xv, pwv, bv, vt);

    scores_mma<<<dim3(SS / 64, NHZ), 256, SC_SM>>>(qp, kp, attnw);

    softmax_kernel<<<NHZ * SS, 256>>>(attnw);

    av_mma<<<dim3(SS / 128, NHZ), 256, AV_SM>>>(attnw, vt, aop);

    proj_mma<2><<<gproj, 256, PJ_SM>>>(aop, pwo, bo, out);
}